// round 8
// baseline (speedup 1.0000x reference)
#include <cuda_runtime.h>
#include <math.h>

#define Bq 4096
#define Sq 512
#define NT 512
#define NB 128
#define RPB 32
#define KST 76               // unified k stride: h[0:64) | x[64:75) | pad
#define HBUFSZ (RPB*KST)     // 2432 floats per h|x buffer

typedef unsigned long long ull;

// shared layout (float offsets)
#define O_WA   0                         // wa [38 kk][64 g~] float4 = 9728
#define O_WB   (O_WA + 38*64*4)          // wb same                  = 9728
#define O_HB   (O_WB + 38*64*4)          // 2 * [32][KST]            = 4864
#define O_WOUT (O_HB + 2*HBUFSZ)         // 128
#define O_SC   (O_WOUT + 128)
#define O_ISC  (O_SC + 32)
#define SM_TOTAL (O_ISC + 32)
#define SMEM_BYTES (SM_TOTAL*4)          // ~98 KB

__device__ __forceinline__ float sigf(float x){ return 1.0f/(1.0f+__expf(-x)); }
__device__ __forceinline__ float tanh_f(float x){ return 2.0f/(1.0f+__expf(-2.0f*x)) - 1.0f; }

__device__ __forceinline__ void ffma2(ull &d, ull a, ull b){
    asm("fma.rn.f32x2 %0, %1, %2, %0;" : "+l"(d) : "l"(a), "l"(b));
}
__device__ __forceinline__ float fold2(ull v){
    float2 f; asm("mov.b64 {%0,%1}, %2;" : "=f"(f.x), "=f"(f.y) : "l"(v));
    return f.x + f.y;
}
__device__ __forceinline__ void gbar(int id){
    asm volatile("bar.sync %0, 128;" :: "r"(id) : "memory");
}

__global__ void __launch_bounds__(NT,1)
deepar_kernel(const float* __restrict__ target,
              const float* __restrict__ covar,
              const int*   __restrict__ cats,
              const float* __restrict__ scale,
              const float* __restrict__ e0,
              const float* __restrict__ e1,
              const float* __restrict__ e2,
              const float* __restrict__ e3,
              const float* __restrict__ w_ih,
              const float* __restrict__ w_hh,
              const float* __restrict__ bias,
              const float* __restrict__ w_out,
              const float* __restrict__ b_out,
              float* __restrict__ out)
{
    extern __shared__ float sm[];
    float* wa_s   = sm + O_WA;
    float* wb_s   = sm + O_WB;
    float* hbuf   = sm + O_HB;
    float* wout_s = sm + O_WOUT;
    float* sc_s   = sm + O_SC;
    float* isc_s  = sm + O_ISC;
    float* sx_s   = sm + O_WA;     // alias: static_x [32][66], pre-phase only

    const int tid  = threadIdx.x;
    const int row0 = blockIdx.x * RPB;

    // ---- phase 0: stage static_x into sx_s (aliases wa_s; weights packed later) ----
    for (int e = tid; e < RPB*65; e += NT){
        int r = e / 65, j = e - r*65;
        int b = row0 + r;
        float v;
        if (j < 64){
            int tsel = j >> 4, jj = j & 15;
            int c = cats[b*4 + tsel];
            const float* et = (tsel==0)?e0:(tsel==1)?e1:(tsel==2)?e2:e3;
            v = et[c*16 + jj];
        } else {
            v = log1pf(scale[b]);
        }
        sx_s[r*66 + j] = v;
    }
    __syncthreads();

    // ---- 16x2 lane grid: group (4 warps) owns 8 rows, covers all 64 gt ----
    const int grp   = tid >> 7;              // 0..3
    const int gLane = tid & 127;             // lane within group
    const int wg    = (tid >> 5) & 3;        // warp within group
    const int lane  = tid & 31;
    const int gl    = lane & 15;             // gate group within warp
    const int rl    = lane >> 4;             // row half
    const int gt    = wg*16 + gl;            // cell column 0..63
    const int grow0 = grp * 8;
    const int rbase = grow0 + rl*4;          // rows rbase..rbase+3

    // ---- pre[j][tp] = bias + static_x @ w_ih[11:76], in registers ----
    float pre[4][4];
    {
        #pragma unroll
        for (int tp = 0; tp < 4; tp++){
            float bv = bias[tp*64 + gt];
            #pragma unroll
            for (int j = 0; j < 4; j++) pre[j][tp] = bv;
        }
        for (int k = 0; k < 65; k++){
            const float* wr = w_ih + (11+k)*256 + gt;
            float w0 = wr[0], w1 = wr[64], w2 = wr[128], w3 = wr[192];
            #pragma unroll
            for (int j = 0; j < 4; j++){
                float xv = sx_s[(rbase+j)*66 + k];
                pre[j][0] = fmaf(xv, w0, pre[j][0]);
                pre[j][1] = fmaf(xv, w1, pre[j][1]);
                pre[j][2] = fmaf(xv, w2, pre[j][2]);
                pre[j][3] = fmaf(xv, w3, pre[j][3]);
            }
        }
    }
    __syncthreads();   // sx readers done; wa_s can be overwritten

    // ---- pack weights: wa[kk][g~] = {i:kpair, f:kpair}, wb = {g:kpair, o:kpair} ----
    for (int idx = tid; idx < 38*64; idx += NT){
        int kk = idx >> 6, g = idx & 63;
        int k0 = 2*kk, k1 = 2*kk + 1;
        #define WK(k,c) ((k) < 64 ? w_hh[(k)*256 + (c)] : ((k) < 75 ? w_ih[((k)-64)*256 + (c)] : 0.0f))
        float4 a4, b4;
        a4.x = WK(k0, g);        a4.y = WK(k1, g);
        a4.z = WK(k0, 64 + g);   a4.w = WK(k1, 64 + g);
        b4.x = WK(k0, 128 + g);  b4.y = WK(k1, 128 + g);
        b4.z = WK(k0, 192 + g);  b4.w = WK(k1, 192 + g);
        #undef WK
        *(float4*)(wa_s + idx*4) = a4;
        *(float4*)(wb_s + idx*4) = b4;
    }
    if (tid < 128) wout_s[tid] = w_out[tid];
    if (tid < RPB){
        float s = scale[row0 + tid];
        sc_s[tid]  = s;
        isc_s[tid] = 1.0f / fmaxf(s, 1e-4f);
    }
    for (int i = tid; i < 2*HBUFSZ; i += NT) hbuf[i] = 0.0f;
    __syncthreads();

    // ---- per-group x ownership: gLane 0..95 cover (8 rows x 12 j) ----
    int xrow = 0, xj = 0, xb = 0;
    const bool xown = (gLane < 96);
    float xreg = 0.0f;
    if (xown){
        xrow = grow0 + (gLane / 12);
        xj   = gLane % 12;
        xb   = row0 + xrow;
        float v = 0.0f;
        if (xj >= 1 && xj <= 10) v = covar[(xb*Sq + 0)*10 + (xj-1)];
        hbuf[1*HBUFSZ + xrow*KST + 64 + xj] = v;   // x(0): prev=0, cov(0)
    }
    // head ownership: gLane 96..111 -> (8 rows x 2 outputs)
    const bool hown = (gLane >= 96) && (gLane < 112);
    const int  hr_  = grow0 + ((gLane - 96) >> 1);
    const int  hws  = gLane & 1;
    __syncthreads();

    const int barid = grp + 1;
    float creg[4] = {0.0f, 0.0f, 0.0f, 0.0f};

    for (int t = 0; t < Sq; t++){
        gbar(barid);   // group-local: h(t-1)/x(t) of rows grow0..grow0+7 visible
        const float* hb = hbuf + ((t+1)&1)*HBUFSZ;   // h(t-1) | x(t)

        // head for step t-1 (reads stable hb rows of this group)
        if (hown && t > 0){
            const float* hr = hb + hr_*KST;
            float a0=0.f,a1=0.f,a2=0.f,a3=0.f;
            #pragma unroll 8
            for (int k = 0; k < 64; k += 4){
                a0 = fmaf(hr[k],   wout_s[2*k     + hws], a0);
                a1 = fmaf(hr[k+1], wout_s[2*(k+1) + hws], a1);
                a2 = fmaf(hr[k+2], wout_s[2*(k+2) + hws], a2);
                a3 = fmaf(hr[k+3], wout_s[2*(k+3) + hws], a3);
            }
            float a = (a0+a1)+(a2+a3) + b_out[hws];
            float sp = (a > 15.0f) ? a : log1pf(__expf(a));
            sp += 1e-4f;
            int b = row0 + hr_;
            if (hws == 0) out[b*Sq + (t-1)] = sp * sc_s[hr_];
            else          out[Bq*Sq + b*Sq + (t-1)] = sp;
        }
        // prefetch x(t+1)
        if (xown && t+1 < Sq){
            if (xj == 0)       xreg = target[xb*Sq + t] * isc_s[xrow];
            else if (xj <= 10) xreg = covar[(xb*Sq + t+1)*10 + (xj-1)];
            else               xreg = 0.0f;
        }

        // ================= GEMM: all 4 gate types for (4 rows x gt) =================
        ull acc[4][4];
        #pragma unroll
        for (int j = 0; j < 4; j++)
            #pragma unroll
            for (int tp = 0; tp < 4; tp++) acc[j][tp] = 0ull;

        #pragma unroll
        for (int kk2 = 0; kk2 < 19; kk2++){
            ulonglong2 wa0 = *(const ulonglong2*)(wa_s + ((2*kk2  )*64 + gt)*4);
            ulonglong2 wb0 = *(const ulonglong2*)(wb_s + ((2*kk2  )*64 + gt)*4);
            ulonglong2 wa1 = *(const ulonglong2*)(wa_s + ((2*kk2+1)*64 + gt)*4);
            ulonglong2 wb1 = *(const ulonglong2*)(wb_s + ((2*kk2+1)*64 + gt)*4);
            #pragma unroll
            for (int j = 0; j < 4; j++){
                ulonglong2 hv = *(const ulonglong2*)(hb + (rbase+j)*KST + kk2*4);
                ffma2(acc[j][0], hv.x, wa0.x);
                ffma2(acc[j][1], hv.x, wa0.y);
                ffma2(acc[j][2], hv.x, wb0.x);
                ffma2(acc[j][3], hv.x, wb0.y);
                ffma2(acc[j][0], hv.y, wa1.x);
                ffma2(acc[j][1], hv.y, wa1.y);
                ffma2(acc[j][2], hv.y, wb1.x);
                ffma2(acc[j][3], hv.y, wb1.y);
            }
        }

        // ================= fused LSTM cell (registers) + h store =================
        {
            float* hw = hbuf + (t&1)*HBUFSZ;
            #pragma unroll
            for (int j = 0; j < 4; j++){
                float gi = fold2(acc[j][0]) + pre[j][0];
                float gf = fold2(acc[j][1]) + pre[j][1];
                float gg = fold2(acc[j][2]) + pre[j][2];
                float go = fold2(acc[j][3]) + pre[j][3];
                float i = sigf(gi);
                float f = sigf(gf);
                float g = tanh_f(gg);
                float o = sigf(go);
                float c = fmaf(f, creg[j], i*g);
                creg[j] = c;
                hw[(rbase+j)*KST + gt] = o * tanh_f(c);
            }
            if (xown) hw[xrow*KST + 64 + xj] = xreg;   // x(t+1)
        }
    }

    // final head for t = Sq-1 (group-local sync, then read hbuf[(Sq-1)&1])
    gbar(barid);
    if (hown){
        const float* hr = hbuf + ((Sq-1)&1)*HBUFSZ + hr_*KST;
        float a0=0.f,a1=0.f,a2=0.f,a3=0.f;
        #pragma unroll 8
        for (int k = 0; k < 64; k += 4){
            a0 = fmaf(hr[k],   wout_s[2*k     + hws], a0);
            a1 = fmaf(hr[k+1], wout_s[2*(k+1) + hws], a1);
            a2 = fmaf(hr[k+2], wout_s[2*(k+2) + hws], a2);
            a3 = fmaf(hr[k+3], wout_s[2*(k+3) + hws], a3);
        }
        float a = (a0+a1)+(a2+a3) + b_out[hws];
        float sp = (a > 15.0f) ? a : log1pf(__expf(a));
        sp += 1e-4f;
        int b = row0 + hr_;
        if (hws == 0) out[b*Sq + (Sq-1)] = sp * sc_s[hr_];
        else          out[Bq*Sq + b*Sq + (Sq-1)] = sp;
    }
}

extern "C" void kernel_launch(void* const* d_in, const int* in_sizes, int n_in,
                              void* d_out, int out_size)
{
    (void)in_sizes; (void)n_in; (void)out_size;
    cudaFuncSetAttribute(deepar_kernel,
                         cudaFuncAttributeMaxDynamicSharedMemorySize, SMEM_BYTES);
    deepar_kernel<<<NB, NT, SMEM_BYTES>>>(
        (const float*)d_in[0],   // target
        (const float*)d_in[1],   // covariates
        (const int*)  d_in[2],   // static_cats
        (const float*)d_in[3],   // scale
        (const float*)d_in[4],   // emb0
        (const float*)d_in[5],   // emb1
        (const float*)d_in[6],   // emb2
        (const float*)d_in[7],   // emb3
        (const float*)d_in[8],   // w_ih
        (const float*)d_in[9],   // w_hh
        (const float*)d_in[10],  // bias
        (const float*)d_in[11],  // w_out
        (const float*)d_in[12],  // b_out
        (float*)d_out);
}